// round 16
// baseline (speedup 1.0000x reference)
#include <cuda_runtime.h>
#include <cuda_fp16.h>
#include <cstdint>

#define NN 100000
#define DD 128
#define EE_MAX 1700000

// Scratch (allocation-free rule: __device__ globals)
__device__ __half g_xh[(size_t)NN * DD];     // fp16 copy of x
__device__ __half g_h1h[(size_t)NN * DD];    // fp16 h1 (only copy)
__device__ __half g_aggh[(size_t)NN * DD];   // fp16 aggregated means
__device__ __half g_wh[4 * 128 * 128];       // fp16 weights: Wn1,Ws1,Wn2,Ws2
__device__ float g_bsum[2][DD];              // bn+bs per layer
__device__ int   g_deg[NN];
__device__ int   g_cursor[NN];
__device__ int   g_rowptr[NN + 1];
__device__ int   g_col[EE_MAX];
__device__ int   g_partial[128];

// ---------------------------------------------------------------------------
__device__ __forceinline__ uint32_t packh2(float a, float b) {
    __half2 h = __floats2half2_rn(a, b);
    return *(uint32_t*)&h;
}

// Heterogeneous prep: deg histogram | x->fp16 | weights->fp16 + bias sums.
__global__ __launch_bounds__(256) void prep_kernel(
    const float* __restrict__ x, const int* __restrict__ dst, int E, int n8,
    const float* __restrict__ Wn1, const float* __restrict__ Ws1,
    const float* __restrict__ Wn2, const float* __restrict__ Ws2,
    const float* __restrict__ bn1, const float* __restrict__ bs1,
    const float* __restrict__ bn2, const float* __restrict__ bs2,
    int nbDeg, int nbCvt) {
    const int b = blockIdx.x;
    if (b < nbDeg) {
        const int e = b * 256 + threadIdx.x;
        if (e < E) atomicAdd(&g_deg[dst[e]], 1);
    } else if (b < nbDeg + nbCvt) {
        const int i = (b - nbDeg) * 256 + threadIdx.x;
        if (i < n8) {
            const float4* p = (const float4*)x + i * 2;
            const float4 v0 = p[0], v1 = p[1];
            uint4 o;
            o.x = packh2(v0.x, v0.y);
            o.y = packh2(v0.z, v0.w);
            o.z = packh2(v1.x, v1.y);
            o.w = packh2(v1.z, v1.w);
            ((uint4*)g_xh)[i] = o;
        }
    } else {
        const int bw = b - nbDeg - nbCvt;            // 0..7
        const int t0 = bw * 256 + threadIdx.x;       // 0..2047
#pragma unroll 1
        for (int i = t0; i < 8192; i += 2048) {      // 8192 uint4 = 65536 halves
            const int m = i >> 11;                   // matrix 0..3
            const int r = i & 2047;                  // uint4 index in matrix
            const float* W = (m == 0) ? Wn1 : (m == 1) ? Ws1 : (m == 2) ? Wn2 : Ws2;
            const float4* p = (const float4*)W + r * 2;
            const float4 v0 = p[0], v1 = p[1];
            uint4 o;
            o.x = packh2(v0.x, v0.y);
            o.y = packh2(v0.z, v0.w);
            o.z = packh2(v1.x, v1.y);
            o.w = packh2(v1.z, v1.w);
            ((uint4*)g_wh)[i] = o;
        }
        if (bw == 0 && threadIdx.x < 128) {
            g_bsum[0][threadIdx.x] = bn1[threadIdx.x] + bs1[threadIdx.x];
            g_bsum[1][threadIdx.x] = bn2[threadIdx.x] + bs2[threadIdx.x];
        }
    }
}

// Block-wise scan of g_deg -> g_rowptr (local exclusive) + block totals.
// Also re-zeros g_deg (next replay).
__global__ __launch_bounds__(1024) void scanA_kernel(int n) {
    const int i = blockIdx.x * 1024 + threadIdx.x;
    const int lane = threadIdx.x & 31;
    const int w = threadIdx.x >> 5;
    const int v = (i < n) ? g_deg[i] : 0;
    int s = v;
#pragma unroll
    for (int o = 1; o < 32; o <<= 1) {
        int t = __shfl_up_sync(0xffffffffu, s, o);
        if (lane >= o) s += t;
    }
    __shared__ int wsum[32];
    if (lane == 31) wsum[w] = s;
    __syncthreads();
    if (w == 0) {
        int ws = wsum[lane];
#pragma unroll
        for (int o = 1; o < 32; o <<= 1) {
            int t = __shfl_up_sync(0xffffffffu, ws, o);
            if (lane >= o) ws += t;
        }
        wsum[lane] = ws;
    }
    __syncthreads();
    const int excl = s - v + (w ? wsum[w - 1] : 0);
    if (i < n) {
        g_rowptr[i] = excl;
        g_deg[i] = 0;
    }
    if (threadIdx.x == 1023) g_partial[blockIdx.x] = excl + v;
}

// Adds the prefix of block totals; also seeds g_cursor with the final rowptr.
__global__ __launch_bounds__(256) void scanC_kernel(int n, int nb) {
    __shared__ int red[256];
    const int t = threadIdx.x;
    const int r = blockIdx.x >> 2;
    red[t] = (t < r) ? g_partial[t] : 0;
    __syncthreads();
#pragma unroll
    for (int o = 128; o > 0; o >>= 1) {
        if (t < o) red[t] += red[t + o];
        __syncthreads();
    }
    const int S = red[0];
    const int i = blockIdx.x * 256 + t;
    if (i < n) {
        const int v = g_rowptr[i] + S;
        g_rowptr[i] = v;
        g_cursor[i] = v;
    }
    if (i == n) {
        int tot = 0;
        for (int j = 0; j < nb; j++) tot += g_partial[j];
        g_rowptr[n] = tot;
    }
}

__global__ void fill_kernel(const int* __restrict__ src, const int* __restrict__ dst, int E) {
    int e = blockIdx.x * blockDim.x + threadIdx.x;
    if (e < E) {
        const int p = atomicAdd(&g_cursor[dst[e]], 1);
        g_col[p] = src[e];
    }
}

// ---------------------------------------------------------------------------
// Paired-neighbor mean aggregation over fp16 features: one warp per node.
// Fully-unrolled 16-iteration window (predicated) -> up to 16 outstanding
// LDG.128 per lane, hiding L2 latency. fp32 accum; fp16 normalized output.
__global__ __launch_bounds__(256) void agg_kernel(const __half* __restrict__ feat,
                                                  __half* __restrict__ out, int n) {
    const int warp = (blockIdx.x * blockDim.x + threadIdx.x) >> 5;
    if (warp >= n) return;
    const int lane = threadIdx.x & 31;
    const int half = lane >> 4;
    const int l16 = lane & 15;
    const int c = l16 << 3;
    const int beg = g_rowptr[warp];
    const int end = g_rowptr[warp + 1];

    float a0 = 0.f, a1 = 0.f, a2 = 0.f, a3 = 0.f;
    float a4 = 0.f, a5 = 0.f, a6 = 0.f, a7 = 0.f;
    for (int base = beg; base < end; base += 32) {
        const int idx = base + lane;
        const int sv = (idx < end) ? g_col[idx] : 0;
        const int cnt = min(end - base, 32);
#pragma unroll
        for (int j = 0; j < 32; j += 2) {
            const int jj = j + half;
            const int s = __shfl_sync(0xffffffffu, sv, jj);
            if (jj < cnt) {
                const uint4 u = *(const uint4*)(feat + (size_t)s * DD + c);
                float2 p;
                p = __half22float2(*(const __half2*)&u.x); a0 += p.x; a1 += p.y;
                p = __half22float2(*(const __half2*)&u.y); a2 += p.x; a3 += p.y;
                p = __half22float2(*(const __half2*)&u.z); a4 += p.x; a5 += p.y;
                p = __half22float2(*(const __half2*)&u.w); a6 += p.x; a7 += p.y;
            }
        }
    }
    a0 += __shfl_down_sync(0xffffffffu, a0, 16);
    a1 += __shfl_down_sync(0xffffffffu, a1, 16);
    a2 += __shfl_down_sync(0xffffffffu, a2, 16);
    a3 += __shfl_down_sync(0xffffffffu, a3, 16);
    a4 += __shfl_down_sync(0xffffffffu, a4, 16);
    a5 += __shfl_down_sync(0xffffffffu, a5, 16);
    a6 += __shfl_down_sync(0xffffffffu, a6, 16);
    a7 += __shfl_down_sync(0xffffffffu, a7, 16);
    if (half == 0) {
        const float inv = 1.0f / fmaxf((float)(end - beg), 1.0f);
        uint4 o;
        o.x = packh2(a0 * inv, a1 * inv);
        o.y = packh2(a2 * inv, a3 * inv);
        o.z = packh2(a4 * inv, a5 * inv);
        o.w = packh2(a6 * inv, a7 * inv);
        *(uint4*)(out + (size_t)warp * DD + c) = o;
    }
}

// ---------------------------------------------------------------------------
// FP16 mma.sync (m16n8k16, fp32 accumulate) fused GEMM + bias(+relu),
// fragments via ldmatrix.m8n8.x4 (R14 structure).
// out[r][o] = relu?( A1[r][:] @ Wn[o][:] + A2[r][:] @ Ws[o][:] + bsum[o] )
// SMEM tile: [k2b (0..3)][row (0..127)] 16B blocks; k2b stride 2080 B.
__device__ __forceinline__ void mma_f16(float* d, const uint32_t* a, const uint32_t* b) {
    asm volatile(
        "mma.sync.aligned.m16n8k16.row.col.f32.f16.f16.f32 "
        "{%0,%1,%2,%3}, {%4,%5,%6,%7}, {%8,%9}, {%0,%1,%2,%3};"
        : "+f"(d[0]), "+f"(d[1]), "+f"(d[2]), "+f"(d[3])
        : "r"(a[0]), "r"(a[1]), "r"(a[2]), "r"(a[3]), "r"(b[0]), "r"(b[1]));
}
#define LDSM_X4(r0, r1, r2, r3, addr)                                          \
    asm volatile("ldmatrix.sync.aligned.m8n8.x4.shared.b16 {%0,%1,%2,%3}, [%4];" \
                 : "=r"(r0), "=r"(r1), "=r"(r2), "=r"(r3) : "r"(addr))

template <bool RELU, bool OUTHALF>
__global__ __launch_bounds__(256) void gemm_kernel(
    const __half* __restrict__ A1, const __half* __restrict__ A2,
    const __half* __restrict__ Wnh, const __half* __restrict__ Wsh,
    const float* __restrict__ bsum,
    float* __restrict__ outf, __half* __restrict__ outh, int n) {
    __shared__ uint32_t sA[4 * 520];
    __shared__ uint32_t sB[4 * 520];

    const int tid = threadIdx.x;
    const int wid = tid >> 5;
    const int lane = tid & 31;
    const int g = lane >> 2;
    const int c = lane & 3;
    const int block_row = blockIdx.x * 128;
    const int m0 = (wid >> 2) * 64;
    const int n0 = (wid & 3) * 32;

    const uint32_t sA_u = (uint32_t)__cvta_generic_to_shared(sA);
    const uint32_t sB_u = (uint32_t)__cvta_generic_to_shared(sB);
    const int lg = lane >> 3;
    const int lr = lane & 7;
    const uint32_t aAddr0 = sA_u + (uint32_t)(lg >> 1) * 2080u
                          + (uint32_t)(m0 + (lg & 1) * 8 + lr) * 16u;
    const uint32_t bAddr0 = sB_u + (uint32_t)(lg & 1) * 2080u
                          + (uint32_t)(n0 + (lg >> 1) * 8 + lr) * 16u;

    float acc[4][4][4];
#pragma unroll
    for (int mt = 0; mt < 4; mt++)
#pragma unroll
        for (int nt = 0; nt < 4; nt++)
#pragma unroll
            for (int q = 0; q < 4; q++) acc[mt][nt][q] = 0.f;

    for (int c0 = 0; c0 < 256; c0 += 32) {
        const __half* aptr = (c0 < 128)
            ? (A1 + (size_t)block_row * DD + c0)
            : (A2 + (size_t)block_row * DD + (c0 - 128));
        const __half* bptr = (c0 < 128) ? (Wnh + c0) : (Wsh + (c0 - 128));

        if (c0) __syncthreads();
#pragma unroll
        for (int i = 0; i < 2; i++) {
            const int s2 = i * 256 + tid;     // 0..511
            const int row = s2 >> 2;          // 0..127
            const int k2b = s2 & 3;           // 8-k block within chunk
            const int so = k2b * 520 + row * 4;

            uint4 h = make_uint4(0u, 0u, 0u, 0u);
            if (block_row + row < n)
                h = *(const uint4*)(aptr + (size_t)row * DD + k2b * 8);
            *(uint4*)(sA + so) = h;

            const uint4 w = *(const uint4*)(bptr + (size_t)row * 128 + k2b * 8);
            *(uint4*)(sB + so) = w;
        }
        __syncthreads();

#pragma unroll
        for (int st = 0; st < 2; st++) {      // two k16 steps per 32-chunk
            const uint32_t stoff = (uint32_t)st * 4160u;
            uint32_t Ar[4][4], Br[2][4];
#pragma unroll
            for (int mt = 0; mt < 4; mt++)
                LDSM_X4(Ar[mt][0], Ar[mt][1], Ar[mt][2], Ar[mt][3],
                        aAddr0 + stoff + (uint32_t)(mt * 256));
#pragma unroll
            for (int np = 0; np < 2; np++)
                LDSM_X4(Br[np][0], Br[np][1], Br[np][2], Br[np][3],
                        bAddr0 + stoff + (uint32_t)(np * 256));
#pragma unroll
            for (int mt = 0; mt < 4; mt++)
#pragma unroll
                for (int nt = 0; nt < 4; nt++)
                    mma_f16(acc[mt][nt], Ar[mt], &Br[nt >> 1][(nt & 1) * 2]);
        }
    }

    // Epilogue: bias + optional relu
#pragma unroll
    for (int nt = 0; nt < 4; nt++) {
        const int col = n0 + nt * 8 + 2 * c;
        const float b0v = bsum[col];
        const float b1v = bsum[col + 1];
#pragma unroll
        for (int mt = 0; mt < 4; mt++) {
            const int r = block_row + m0 + mt * 16 + g;
            float v0 = acc[mt][nt][0] + b0v;
            float v1 = acc[mt][nt][1] + b1v;
            float v2 = acc[mt][nt][2] + b0v;
            float v3 = acc[mt][nt][3] + b1v;
            if (RELU) {
                v0 = fmaxf(v0, 0.f); v1 = fmaxf(v1, 0.f);
                v2 = fmaxf(v2, 0.f); v3 = fmaxf(v3, 0.f);
            }
            if (r < n) {
                if (OUTHALF) {
                    *(uint32_t*)(outh + (size_t)r * DD + col) = packh2(v0, v1);
                } else {
                    *(float2*)(outf + (size_t)r * DD + col) = make_float2(v0, v1);
                }
            }
            if (r + 8 < n) {
                if (OUTHALF) {
                    *(uint32_t*)(outh + (size_t)(r + 8) * DD + col) = packh2(v2, v3);
                } else {
                    *(float2*)(outf + (size_t)(r + 8) * DD + col) = make_float2(v2, v3);
                }
            }
        }
    }
}

// ---------------------------------------------------------------------------
extern "C" void kernel_launch(void* const* d_in, const int* in_sizes, int n_in,
                              void* d_out, int out_size) {
    const float* x   = (const float*)d_in[0];
    const int* ei    = (const int*)d_in[1];
    const float* Wn1 = (const float*)d_in[2];
    const float* bn1 = (const float*)d_in[3];
    const float* Ws1 = (const float*)d_in[4];
    const float* bs1 = (const float*)d_in[5];
    const float* Wn2 = (const float*)d_in[6];
    const float* bn2 = (const float*)d_in[7];
    const float* Ws2 = (const float*)d_in[8];
    const float* bs2 = (const float*)d_in[9];
    float* out = (float*)d_out;

    const int n = in_sizes[0] / DD;
    const int E = in_sizes[1] / 2;
    const int* src = ei;
    const int* dst = ei + E;

    __half* d_xh;   cudaGetSymbolAddress((void**)&d_xh, g_xh);
    __half* d_h1h;  cudaGetSymbolAddress((void**)&d_h1h, g_h1h);
    __half* d_aggh; cudaGetSymbolAddress((void**)&d_aggh, g_aggh);
    __half* d_wh;   cudaGetSymbolAddress((void**)&d_wh, g_wh);
    float* d_bsum;  cudaGetSymbolAddress((void**)&d_bsum, g_bsum);

    const int threads = 256;
    const int nb = (n + 1023) / 1024;
    const int n8 = (n * DD) / 8;
    const int nbDeg = (E + 255) / 256;
    const int nbCvt = (n8 + 255) / 256;

    // --- prep (deg + x->fp16 + weights->fp16 + bias) + CSR build ---
    prep_kernel<<<nbDeg + nbCvt + 8, threads>>>(
        x, dst, E, n8, Wn1, Ws1, Wn2, Ws2, bn1, bs1, bn2, bs2, nbDeg, nbCvt);
    scanA_kernel<<<nb, 1024>>>(n);
    scanC_kernel<<<(n + 1 + threads - 1) / threads, threads>>>(n, nb);
    fill_kernel<<<(E + threads - 1) / threads, threads>>>(src, dst, E);

    const unsigned agg_blocks = ((unsigned)n * 32u + threads - 1) / threads;
    const int gemm_blocks = (n + 127) / 128;

    // layer 1: mean-aggregate x_h -> agg_h, GEMM + bias + relu -> h1 (fp16)
    agg_kernel<<<agg_blocks, threads>>>(d_xh, d_aggh, n);
    gemm_kernel<true, true><<<gemm_blocks, 256>>>(
        d_aggh, d_xh, d_wh, d_wh + 16384, d_bsum, nullptr, d_h1h, n);

    // layer 2: mean-aggregate h1_h -> agg_h, GEMM + bias -> out (fp32)
    agg_kernel<<<agg_blocks, threads>>>(d_h1h, d_aggh, n);
    gemm_kernel<false, false><<<gemm_blocks, 256>>>(
        d_aggh, d_h1h, d_wh + 2 * 16384, d_wh + 3 * 16384, d_bsum + DD, out, nullptr, n);
}

// round 17
// speedup vs baseline: 1.1659x; 1.1659x over previous
#include <cuda_runtime.h>
#include <cuda_fp16.h>
#include <cstdint>

#define NN 100000
#define DD 128
#define EE_MAX 1700000

// Scratch (allocation-free rule: __device__ globals)
__device__ __half g_xh[(size_t)NN * DD];     // fp16 copy of x
__device__ __half g_h1h[(size_t)NN * DD];    // fp16 h1 (only copy)
__device__ __half g_aggh[(size_t)NN * DD];   // fp16 aggregated means
__device__ __half g_wh[4 * 128 * 128];       // fp16 weights: Wn1,Ws1,Wn2,Ws2
__device__ float g_bsum[2][DD];              // bn+bs per layer
__device__ int   g_deg[NN];
__device__ int   g_cursor[NN];
__device__ int   g_rowptr[NN + 1];
__device__ int   g_col[EE_MAX];
__device__ int   g_aggv[128];                // per-block scan aggregates
__device__ volatile int g_flag[128];         // lookback flags (reset in prep)

// ---------------------------------------------------------------------------
__device__ __forceinline__ uint32_t packh2(float a, float b) {
    __half2 h = __floats2half2_rn(a, b);
    return *(uint32_t*)&h;
}

// Heterogeneous prep: deg histogram | x->fp16 | weights->fp16 + bias + flags.
__global__ __launch_bounds__(256) void prep_kernel(
    const float* __restrict__ x, const int* __restrict__ dst, int E, int n8,
    const float* __restrict__ Wn1, const float* __restrict__ Ws1,
    const float* __restrict__ Wn2, const float* __restrict__ Ws2,
    const float* __restrict__ bn1, const float* __restrict__ bs1,
    const float* __restrict__ bn2, const float* __restrict__ bs2,
    int nbDeg, int nbCvt) {
    const int b = blockIdx.x;
    if (b < nbDeg) {
        const int e = b * 256 + threadIdx.x;
        if (e < E) atomicAdd(&g_deg[dst[e]], 1);
    } else if (b < nbDeg + nbCvt) {
        const int i = (b - nbDeg) * 256 + threadIdx.x;
        if (i < n8) {
            const float4* p = (const float4*)x + i * 2;
            const float4 v0 = p[0], v1 = p[1];
            uint4 o;
            o.x = packh2(v0.x, v0.y);
            o.y = packh2(v0.z, v0.w);
            o.z = packh2(v1.x, v1.y);
            o.w = packh2(v1.z, v1.w);
            ((uint4*)g_xh)[i] = o;
        }
    } else {
        const int bw = b - nbDeg - nbCvt;            // 0..7
        const int t0 = bw * 256 + threadIdx.x;       // 0..2047
#pragma unroll 1
        for (int i = t0; i < 8192; i += 2048) {      // 8192 uint4 = 65536 halves
            const int m = i >> 11;                   // matrix 0..3
            const int r = i & 2047;                  // uint4 index in matrix
            const float* W = (m == 0) ? Wn1 : (m == 1) ? Ws1 : (m == 2) ? Wn2 : Ws2;
            const float4* p = (const float4*)W + r * 2;
            const float4 v0 = p[0], v1 = p[1];
            uint4 o;
            o.x = packh2(v0.x, v0.y);
            o.y = packh2(v0.z, v0.w);
            o.z = packh2(v1.x, v1.y);
            o.w = packh2(v1.z, v1.w);
            ((uint4*)g_wh)[i] = o;
        }
        if (bw == 0 && threadIdx.x < 128) {
            g_bsum[0][threadIdx.x] = bn1[threadIdx.x] + bs1[threadIdx.x];
            g_bsum[1][threadIdx.x] = bn2[threadIdx.x] + bs2[threadIdx.x];
            g_flag[threadIdx.x] = 0;                 // reset lookback flags
        }
    }
}

// Single-pass scan with decoupled lookback (all nb<=98 blocks co-resident).
// g_deg -> g_rowptr exclusive prefix; seeds g_cursor; re-zeros g_deg.
__global__ __launch_bounds__(1024) void scan_kernel(int n, int nb) {
    const int b = blockIdx.x;
    const int i = b * 1024 + threadIdx.x;
    const int lane = threadIdx.x & 31;
    const int w = threadIdx.x >> 5;
    const int v = (i < n) ? g_deg[i] : 0;
    int s = v;
#pragma unroll
    for (int o = 1; o < 32; o <<= 1) {
        int t = __shfl_up_sync(0xffffffffu, s, o);
        if (lane >= o) s += t;
    }
    __shared__ int wsum[32];
    if (lane == 31) wsum[w] = s;
    __syncthreads();
    if (w == 0) {
        int ws = wsum[lane];
#pragma unroll
        for (int o = 1; o < 32; o <<= 1) {
            int t = __shfl_up_sync(0xffffffffu, ws, o);
            if (lane >= o) ws += t;
        }
        wsum[lane] = ws;
    }
    __syncthreads();
    const int excl = s - v + (w ? wsum[w - 1] : 0);

    // publish this block's aggregate
    if (threadIdx.x == 1023) {
        g_aggv[b] = excl + v;
        __threadfence();
        g_flag[b] = 1;
    }
    // lookback: first 128 threads poll predecessors and reduce
    __shared__ int wred[4];
    if (threadIdx.x < 128) {
        int pv = 0;
        if ((int)threadIdx.x < b) {
            while (g_flag[threadIdx.x] == 0) {}
            pv = g_aggv[threadIdx.x];
        }
#pragma unroll
        for (int o = 16; o > 0; o >>= 1)
            pv += __shfl_down_sync(0xffffffffu, pv, o);
        if (lane == 0) wred[w] = pv;
    }
    __syncthreads();
    const int S = wred[0] + wred[1] + wred[2] + wred[3];

    if (i < n) {
        const int val = excl + S;
        g_rowptr[i] = val;
        g_cursor[i] = val;
        g_deg[i] = 0;           // ready for next replay
    }
    if (b == nb - 1 && threadIdx.x == 1023)
        g_rowptr[n] = S + excl + v;
}

__global__ void fill_kernel(const int* __restrict__ src, const int* __restrict__ dst, int E) {
    int e = blockIdx.x * blockDim.x + threadIdx.x;
    if (e < E) {
        const int p = atomicAdd(&g_cursor[dst[e]], 1);
        g_col[p] = src[e];
    }
}

// ---------------------------------------------------------------------------
// Paired-neighbor mean aggregation over fp16 features: one warp per node.
__global__ __launch_bounds__(256) void agg_kernel(const __half* __restrict__ feat,
                                                  __half* __restrict__ out, int n) {
    const int warp = (blockIdx.x * blockDim.x + threadIdx.x) >> 5;
    if (warp >= n) return;
    const int lane = threadIdx.x & 31;
    const int half = lane >> 4;
    const int l16 = lane & 15;
    const int c = l16 << 3;
    const int beg = g_rowptr[warp];
    const int end = g_rowptr[warp + 1];

    float a0 = 0.f, a1 = 0.f, a2 = 0.f, a3 = 0.f;
    float a4 = 0.f, a5 = 0.f, a6 = 0.f, a7 = 0.f;
    for (int base = beg; base < end; base += 32) {
        const int idx = base + lane;
        const int sv = (idx < end) ? g_col[idx] : 0;
        const int cnt = min(end - base, 32);
#pragma unroll 4
        for (int j = 0; j < cnt; j += 2) {
            const int jj = j + half;
            const int s = __shfl_sync(0xffffffffu, sv, jj);
            if (jj < cnt) {
                const uint4 u = *(const uint4*)(feat + (size_t)s * DD + c);
                float2 p;
                p = __half22float2(*(const __half2*)&u.x); a0 += p.x; a1 += p.y;
                p = __half22float2(*(const __half2*)&u.y); a2 += p.x; a3 += p.y;
                p = __half22float2(*(const __half2*)&u.z); a4 += p.x; a5 += p.y;
                p = __half22float2(*(const __half2*)&u.w); a6 += p.x; a7 += p.y;
            }
        }
    }
    a0 += __shfl_down_sync(0xffffffffu, a0, 16);
    a1 += __shfl_down_sync(0xffffffffu, a1, 16);
    a2 += __shfl_down_sync(0xffffffffu, a2, 16);
    a3 += __shfl_down_sync(0xffffffffu, a3, 16);
    a4 += __shfl_down_sync(0xffffffffu, a4, 16);
    a5 += __shfl_down_sync(0xffffffffu, a5, 16);
    a6 += __shfl_down_sync(0xffffffffu, a6, 16);
    a7 += __shfl_down_sync(0xffffffffu, a7, 16);
    if (half == 0) {
        const float inv = 1.0f / fmaxf((float)(end - beg), 1.0f);
        uint4 o;
        o.x = packh2(a0 * inv, a1 * inv);
        o.y = packh2(a2 * inv, a3 * inv);
        o.z = packh2(a4 * inv, a5 * inv);
        o.w = packh2(a6 * inv, a7 * inv);
        *(uint4*)(out + (size_t)warp * DD + c) = o;
    }
}

// ---------------------------------------------------------------------------
// FP16 mma.sync GEMM, software-pipelined staging (LDG for chunk c+1 issued
// before the MMAs of chunk c; STS after; one sync per chunk; double-buffered).
// out[r][o] = relu?( A1[r][:] @ Wn[o][:] + A2[r][:] @ Ws[o][:] + bsum[o] )
// Per-chunk SMEM layout (uint32): [k2b (0..3) stride 520][row (0..127) * 4].
__device__ __forceinline__ void mma_f16(float* d, const uint32_t* a, const uint32_t* b) {
    asm volatile(
        "mma.sync.aligned.m16n8k16.row.col.f32.f16.f16.f32 "
        "{%0,%1,%2,%3}, {%4,%5,%6,%7}, {%8,%9}, {%0,%1,%2,%3};"
        : "+f"(d[0]), "+f"(d[1]), "+f"(d[2]), "+f"(d[3])
        : "r"(a[0]), "r"(a[1]), "r"(a[2]), "r"(a[3]), "r"(b[0]), "r"(b[1]));
}
#define LDSM_X4(r0, r1, r2, r3, addr)                                          \
    asm volatile("ldmatrix.sync.aligned.m8n8.x4.shared.b16 {%0,%1,%2,%3}, [%4];" \
                 : "=r"(r0), "=r"(r1), "=r"(r2), "=r"(r3) : "r"(addr))

template <bool RELU, bool OUTHALF>
__global__ __launch_bounds__(256) void gemm_kernel(
    const __half* __restrict__ A1, const __half* __restrict__ A2,
    const __half* __restrict__ Wnh, const __half* __restrict__ Wsh,
    const float* __restrict__ bsum,
    float* __restrict__ outf, __half* __restrict__ outh, int n) {
    __shared__ uint32_t sA[2 * 2080];
    __shared__ uint32_t sB[2 * 2080];

    const int tid = threadIdx.x;
    const int wid = tid >> 5;
    const int lane = tid & 31;
    const int g = lane >> 2;
    const int c = lane & 3;
    const int block_row = blockIdx.x * 128;
    const int m0 = (wid >> 2) * 64;
    const int n0 = (wid & 3) * 32;

    // staging mapping (2 slots per thread)
    const int row0 = tid >> 2;              // slot i row = row0 + i*64? No:
    // keep R14 mapping: slot s2 = i*256 + tid -> row = s2>>2, k2b = s2&3
    auto ldAB = [&](int ch, uint4* ra, uint4* rb) {
        const __half* aptr = (ch < 4)
            ? (A1 + (size_t)block_row * DD + ch * 32)
            : (A2 + (size_t)block_row * DD + (ch - 4) * 32);
        const __half* bptr = (ch < 4) ? (Wnh + ch * 32) : (Wsh + (ch - 4) * 32);
#pragma unroll
        for (int i = 0; i < 2; i++) {
            const int s2 = i * 256 + tid;
            const int row = s2 >> 2;
            const int k2b = s2 & 3;
            ra[i] = make_uint4(0u, 0u, 0u, 0u);
            if (block_row + row < n)
                ra[i] = *(const uint4*)(aptr + (size_t)row * DD + k2b * 8);
            rb[i] = *(const uint4*)(bptr + (size_t)row * 128 + k2b * 8);
        }
    };
    auto stAB = [&](int buf, const uint4* ra, const uint4* rb) {
#pragma unroll
        for (int i = 0; i < 2; i++) {
            const int s2 = i * 256 + tid;
            const int row = s2 >> 2;
            const int k2b = s2 & 3;
            const int so = buf * 2080 + k2b * 520 + row * 4;
            *(uint4*)(sA + so) = ra[i];
            *(uint4*)(sB + so) = rb[i];
        }
    };

    const uint32_t sA_u = (uint32_t)__cvta_generic_to_shared(sA);
    const uint32_t sB_u = (uint32_t)__cvta_generic_to_shared(sB);
    const int lg = lane >> 3;
    const int lr = lane & 7;
    const uint32_t aFrag = (uint32_t)(lg >> 1) * 2080u
                         + (uint32_t)(m0 + (lg & 1) * 8 + lr) * 16u;
    const uint32_t bFrag = (uint32_t)(lg & 1) * 2080u
                         + (uint32_t)(n0 + (lg >> 1) * 8 + lr) * 16u;

    float acc[4][4][4];
#pragma unroll
    for (int mt = 0; mt < 4; mt++)
#pragma unroll
        for (int nt = 0; nt < 4; nt++)
#pragma unroll
            for (int q = 0; q < 4; q++) acc[mt][nt][q] = 0.f;

    uint4 ra[2], rb[2];
    ldAB(0, ra, rb);
    stAB(0, ra, rb);
    __syncthreads();

#pragma unroll 1
    for (int ch = 0; ch < 8; ch++) {
        // prefetch next chunk into registers (overlaps with MMAs below)
        if (ch < 7) ldAB(ch + 1, ra, rb);

        const uint32_t bufOff = (uint32_t)((ch & 1) * 8320);
        const uint32_t aBase = sA_u + bufOff + aFrag;
        const uint32_t bBase = sB_u + bufOff + bFrag;
#pragma unroll
        for (int st = 0; st < 2; st++) {
            const uint32_t stoff = (uint32_t)st * 4160u;
            uint32_t Ar[4][4], Br[2][4];
#pragma unroll
            for (int mt = 0; mt < 4; mt++)
                LDSM_X4(Ar[mt][0], Ar[mt][1], Ar[mt][2], Ar[mt][3],
                        aBase + stoff + (uint32_t)(mt * 256));
#pragma unroll
            for (int np = 0; np < 2; np++)
                LDSM_X4(Br[np][0], Br[np][1], Br[np][2], Br[np][3],
                        bBase + stoff + (uint32_t)(np * 256));
#pragma unroll
            for (int mt = 0; mt < 4; mt++)
#pragma unroll
                for (int nt = 0; nt < 4; nt++)
                    mma_f16(acc[mt][nt], Ar[mt], &Br[nt >> 1][(nt & 1) * 2]);
        }

        if (ch < 7) stAB((ch + 1) & 1, ra, rb);
        __syncthreads();
    }

    // Epilogue: bias + optional relu
#pragma unroll
    for (int nt = 0; nt < 4; nt++) {
        const int col = n0 + nt * 8 + 2 * c;
        const float b0v = bsum[col];
        const float b1v = bsum[col + 1];
#pragma unroll
        for (int mt = 0; mt < 4; mt++) {
            const int r = block_row + m0 + mt * 16 + g;
            float v0 = acc[mt][nt][0] + b0v;
            float v1 = acc[mt][nt][1] + b1v;
            float v2 = acc[mt][nt][2] + b0v;
            float v3 = acc[mt][nt][3] + b1v;
            if (RELU) {
                v0 = fmaxf(v0, 0.f); v1 = fmaxf(v1, 0.f);
                v2 = fmaxf(v2, 0.f); v3 = fmaxf(v3, 0.f);
            }
            if (r < n) {
                if (OUTHALF) {
                    *(uint32_t*)(outh + (size_t)r * DD + col) = packh2(v0, v1);
                } else {
                    *(float2*)(outf + (size_t)r * DD + col) = make_float2(v0, v1);
                }
            }
            if (r + 8 < n) {
                if (OUTHALF) {
                    *(uint32_t*)(outh + (size_t)(r + 8) * DD + col) = packh2(v2, v3);
                } else {
                    *(float2*)(outf + (size_t)(r + 8) * DD + col) = make_float2(v2, v3);
                }
            }
        }
    }
}

// ---------------------------------------------------------------------------
extern "C" void kernel_launch(void* const* d_in, const int* in_sizes, int n_in,
                              void* d_out, int out_size) {
    const float* x   = (const float*)d_in[0];
    const int* ei    = (const int*)d_in[1];
    const float* Wn1 = (const float*)d_in[2];
    const float* bn1 = (const float*)d_in[3];
    const float* Ws1 = (const float*)d_in[4];
    const float* bs1 = (const float*)d_in[5];
    const float* Wn2 = (const float*)d_in[6];
    const float* bn2 = (const float*)d_in[7];
    const float* Ws2 = (const float*)d_in[8];
    const float* bs2 = (const float*)d_in[9];
    float* out = (float*)d_out;

    const int n = in_sizes[0] / DD;
    const int E = in_sizes[1] / 2;
    const int* src = ei;
    const int* dst = ei + E;

    __half* d_xh;   cudaGetSymbolAddress((void**)&d_xh, g_xh);
    __half* d_h1h;  cudaGetSymbolAddress((void**)&d_h1h, g_h1h);
    __half* d_aggh; cudaGetSymbolAddress((void**)&d_aggh, g_aggh);
    __half* d_wh;   cudaGetSymbolAddress((void**)&d_wh, g_wh);
    float* d_bsum;  cudaGetSymbolAddress((void**)&d_bsum, g_bsum);

    const int threads = 256;
    const int nb = (n + 1023) / 1024;
    const int n8 = (n * DD) / 8;
    const int nbDeg = (E + 255) / 256;
    const int nbCvt = (n8 + 255) / 256;

    // --- prep (deg + x->fp16 + weights->fp16 + bias + flag reset) ---
    prep_kernel<<<nbDeg + nbCvt + 8, threads>>>(
        x, dst, E, n8, Wn1, Ws1, Wn2, Ws2, bn1, bs1, bn2, bs2, nbDeg, nbCvt);
    // --- single-pass scan (rowptr + cursor seed + deg reset) ---
    scan_kernel<<<nb, 1024>>>(n, nb);
    fill_kernel<<<(E + threads - 1) / threads, threads>>>(src, dst, E);

    const unsigned agg_blocks = ((unsigned)n * 32u + threads - 1) / threads;
    const int gemm_blocks = (n + 127) / 128;

    // layer 1: mean-aggregate x_h -> agg_h, GEMM + bias + relu -> h1 (fp16)
    agg_kernel<<<agg_blocks, threads>>>(d_xh, d_aggh, n);
    gemm_kernel<true, true><<<gemm_blocks, 256>>>(
        d_aggh, d_xh, d_wh, d_wh + 16384, d_bsum, nullptr, d_h1h, n);

    // layer 2: mean-aggregate h1_h -> agg_h, GEMM + bias -> out (fp32)
    agg_kernel<<<agg_blocks, threads>>>(d_h1h, d_aggh, n);
    gemm_kernel<false, false><<<gemm_blocks, 256>>>(
        d_aggh, d_h1h, d_wh + 2 * 16384, d_wh + 3 * 16384, d_bsum + DD, out, nullptr, n);
}